// round 17
// baseline (speedup 1.0000x reference)
#include <cuda_runtime.h>
#include <cuda_fp16.h>
#include <cstdint>

// Problem shape (fixed for this instance)
#define B_    16
#define N_    4096
#define S_    1024
#define C2_   256
#define C1_   128
#define CIN_  384      // C2_ + C1_
#define M1_   256
#define M2_   128
#define MROWS (B_ * N_)   // 65536

// ---------------------------------------------------------------------------
// Scratch (static __device__ globals)
// ---------------------------------------------------------------------------
__device__ __half g_xh [(size_t)MROWS * CIN_];   // concat input, fp16
__device__ __half g_y1h[(size_t)MROWS * M1_];    // conv1 raw output, fp16
__device__ __half g_w1h[M1_ * CIN_];
__device__ __half g_w2h[M2_ * M1_];
__device__ int4   g_idx[MROWS];                  // 3-NN indices per point
__device__ float4 g_w4 [MROWS];                  // normalized weights per point
__device__ float g_sum1[M1_], g_sq1[M1_];
__device__ float g_sum2[M2_], g_sq2[M2_];

// ---------------------------------------------------------------------------
// PTX helpers — all baseline compute_80-level
// ---------------------------------------------------------------------------
__device__ __forceinline__ unsigned smem_u32(const void* p) {
    unsigned a;
    asm("{ .reg .u64 t; cvta.to.shared.u64 t, %1; cvt.u32.u64 %0, t; }"
        : "=r"(a) : "l"(p));
    return a;
}
__device__ __forceinline__ void cp16(unsigned dst, const void* src) {
    asm volatile("cp.async.cg.shared.global [%0], [%1], 16;"
                 :: "r"(dst), "l"(src) : "memory");
}
__device__ __forceinline__ void cp_commit() {
    asm volatile("cp.async.commit_group;" ::: "memory");
}
template <int N>
__device__ __forceinline__ void cp_wait() {
    asm volatile("cp.async.wait_group %0;" :: "n"(N) : "memory");
}
__device__ __forceinline__ void ldsm4(unsigned* r, unsigned addr) {
    asm volatile("ldmatrix.sync.aligned.m8n8.x4.shared.b16 {%0,%1,%2,%3}, [%4];"
                 : "=r"(r[0]), "=r"(r[1]), "=r"(r[2]), "=r"(r[3]) : "r"(addr));
}
__device__ __forceinline__ void mma16816(float* d, const unsigned* a,
                                         unsigned b0, unsigned b1) {
    asm volatile(
        "mma.sync.aligned.m16n8k16.row.col.f32.f16.f16.f32 "
        "{%0,%1,%2,%3}, {%4,%5,%6,%7}, {%8,%9}, {%0,%1,%2,%3};"
        : "+f"(d[0]), "+f"(d[1]), "+f"(d[2]), "+f"(d[3])
        : "r"(a[0]), "r"(a[1]), "r"(a[2]), "r"(a[3]), "r"(b0), "r"(b1));
}
__device__ __forceinline__ unsigned h2u(__half2 h) {
    return *reinterpret_cast<unsigned*>(&h);
}

// ---------------------------------------------------------------------------
// prep (launch 0): W1,W2 -> fp16, zero BN stats, skip channels -> g_xh fp16
// ---------------------------------------------------------------------------
#define SKIPH2 (MROWS * 64)            // 4194304 half2 slots for skip
__global__ void prep_kernel(const float* __restrict__ W1,
                            const float* __restrict__ W2,
                            const float* __restrict__ skip)
{
    const int idx = blockIdx.x * 256 + threadIdx.x;
    if (idx < 256) {
        if (idx < M1_) { g_sum1[idx] = 0.f; g_sq1[idx] = 0.f; }
        if (idx < M2_) { g_sum2[idx] = 0.f; g_sq2[idx] = 0.f; }
    }
    if (idx < SKIPH2) {
        const int row = idx >> 6, c = idx & 63;
        float2 sv = *(const float2*)(skip + (size_t)row * C1_ + 2 * c);
        *((__half2*)(g_xh + (size_t)row * CIN_) + 128 + c) =
            __floats2half2_rn(sv.x, sv.y);
    } else {
        const int j = idx - SKIPH2;
        if (j < M1_ * CIN_) {
            g_w1h[j] = __float2half(W1[j]);
        } else {
            const int k = j - M1_ * CIN_;
            if (k < M2_ * M1_) g_w2h[k] = __float2half(W2[k]);
        }
    }
}

// ---------------------------------------------------------------------------
// knn (launch 1): top-3 NN, 2 points per thread (shared LDS amortized)
// ---------------------------------------------------------------------------
__global__ void knn_kernel(const float* __restrict__ txyz,
                           const float* __restrict__ sxyz)
{
    __shared__ float4 s_src[S_];
    const int b   = blockIdx.y;
    const int p0  = blockIdx.x * 256;
    const int tid = threadIdx.x;

    const float* sx = sxyz + (size_t)b * S_ * 3;
    for (int i = tid; i < S_; i += 128) {
        float x = sx[i * 3 + 0], y = sx[i * 3 + 1], z = sx[i * 3 + 2];
        s_src[i] = make_float4(x, y, z, x * x + y * y + z * z);
    }
    __syncthreads();

    const int nA = p0 + tid, nB = p0 + tid + 128;
    const float* tpA = txyz + ((size_t)b * N_ + nA) * 3;
    const float* tpB = txyz + ((size_t)b * N_ + nB) * 3;
    const float ax = tpA[0], ay = tpA[1], az = tpA[2];
    const float bx = tpB[0], by = tpB[1], bz = tpB[2];
    const float qa = ax * ax + ay * ay + az * az;
    const float qb = bx * bx + by * by + bz * bz;

    float a0 = 3.4e38f, a1 = 3.4e38f, a2 = 3.4e38f;
    float b0 = 3.4e38f, b1 = 3.4e38f, b2 = 3.4e38f;
    int   ai0 = 0, ai1 = 0, ai2 = 0, bi0 = 0, bi1 = 0, bi2 = 0;
    #pragma unroll 4
    for (int s = 0; s < S_; ++s) {
        float4 v = s_src[s];
        float crA = ax * v.x + ay * v.y + az * v.z;
        float crB = bx * v.x + by * v.y + bz * v.z;
        float dA = fmaxf(qa + v.w - 2.f * crA, 0.f);
        float dB = fmaxf(qb + v.w - 2.f * crB, 0.f);
        if (dA < a2) {
            if (dA < a1) {
                a2 = a1; ai2 = ai1;
                if (dA < a0) { a1 = a0; ai1 = ai0; a0 = dA; ai0 = s; }
                else         { a1 = dA; ai1 = s; }
            } else { a2 = dA; ai2 = s; }
        }
        if (dB < b2) {
            if (dB < b1) {
                b2 = b1; bi2 = bi1;
                if (dB < b0) { b1 = b0; bi1 = bi0; b0 = dB; bi0 = s; }
                else         { b1 = dB; bi1 = s; }
            } else { b2 = dB; bi2 = s; }
        }
    }

    #pragma unroll
    for (int pt = 0; pt < 2; ++pt) {
        const int   n  = pt ? nB : nA;
        const float tx = pt ? bx : ax, ty = pt ? by : ay, tz = pt ? bz : az;
        int ii[3];
        if (pt) { ii[0] = bi0; ii[1] = bi1; ii[2] = bi2; }
        else    { ii[0] = ai0; ii[1] = ai1; ii[2] = ai2; }
        float w[3], wsum = 0.f;
        #pragma unroll
        for (int k = 0; k < 3; ++k) {
            float4 v = s_src[ii[k]];
            float dx = tx - v.x, dy = ty - v.y, dz = tz - v.z;
            float dd = dx * dx + dy * dy + dz * dz;
            w[k] = 1.f / (dd + 1e-8f);
            wsum += w[k];
        }
        const float inv = 1.f / wsum;
        const size_t row = (size_t)b * N_ + n;
        g_idx[row] = make_int4(ii[0], ii[1], ii[2], 0);
        g_w4[row]  = make_float4(w[0] * inv, w[1] * inv, w[2] * inv, 0.f);
    }
}

// ---------------------------------------------------------------------------
// gather (launch 2): one warp per point; float4-wide weighted gather -> g_xh
// ---------------------------------------------------------------------------
__global__ void gather_kernel(const float* __restrict__ sfeat)
{
    const int wid  = threadIdx.x >> 5;
    const int lane = threadIdx.x & 31;
    const int row  = blockIdx.x * 8 + wid;

    const int4   iv = g_idx[row];
    const float4 wv = g_w4[row];
    const float* F  = sfeat + (size_t)(row >> 12) * S_ * C2_;   // N_=4096
    const float4* f0 = (const float4*)(F + (size_t)iv.x * C2_);
    const float4* f1 = (const float4*)(F + (size_t)iv.y * C2_);
    const float4* f2 = (const float4*)(F + (size_t)iv.z * C2_);
    uint2* xd = (uint2*)(g_xh + (size_t)row * CIN_);

    #pragma unroll
    for (int t = 0; t < 2; ++t) {
        const int c4 = lane + 32 * t;          // float4 index over 256 channels
        float4 a = f0[c4], b = f1[c4], c = f2[c4];
        float rx = wv.x * a.x + wv.y * b.x + wv.z * c.x;
        float ry = wv.x * a.y + wv.y * b.y + wv.z * c.y;
        float rz = wv.x * a.z + wv.y * b.z + wv.z * c.z;
        float rw = wv.x * a.w + wv.y * b.w + wv.z * c.w;
        xd[c4] = make_uint2(h2u(__floats2half2_rn(rx, ry)),
                            h2u(__floats2half2_rn(rz, rw)));
    }
}

// ---------------------------------------------------------------------------
// mma.sync GEMM (fp16): CTA tile 128x128x32, 8 warps (2M x 4N), warp 64x32.
//   FIRST : A = g_xh via cp.async; C = g_y1h (fp16); stats1. grid (2, 512).
//   SECOND: A = g_y1h -> BN1+ReLU in producer; C = out fp32; stats2. grid (1, 512).
// 4-stage cp.async pipeline; rows 32 fp16 + 16 pad = 80 B.
// ---------------------------------------------------------------------------
#define APL_   (128 * 80)
#define BPL_   (128 * 80)
#define STG_   (APL_ + BPL_)          // 20480
#define REDO_  81920                  // max(4*STG_=81920, Ct=128*132*4=67584)
#define SCO_   (REDO_ + 1024)

template <int K, int NOUT, bool SECOND>
__global__ void __launch_bounds__(256, 2)
gemm_mma_kernel(float* __restrict__ outp,
                const float* __restrict__ gamma, const float* __restrict__ beta)
{
    constexpr int NC = K / 32;

    extern __shared__ char sm[];
    const unsigned sb = smem_u32(sm);

    const int tid  = threadIdx.x;
    const int wid  = tid >> 5;
    const int lane = tid & 31;
    const int warpM = wid & 1;
    const int warpN = wid >> 1;
    const int n0 = blockIdx.x * 128;
    const size_t m0 = (size_t)blockIdx.y * 128;

    const __half* Wh = SECOND ? g_w2h : g_w1h;
    float* gsum = SECOND ? g_sum2 : g_sum1;
    float* gsq  = SECOND ? g_sq2  : g_sq1;

    float* redsum = (float*)(sm + REDO_);
    float* redsq  = redsum + 128;
    float* s_sc   = (float*)(sm + SCO_);
    float* s_sh   = s_sc + K;

    if (SECOND && tid < K) {             // BN1 coefficients from raw sums
        const float invC = 1.0f / (float)MROWS;
        float mean = g_sum1[tid] * invC;
        float var  = g_sq1[tid] * invC - mean * mean;
        float sc   = gamma[tid] * rsqrtf(var + 1e-5f);
        s_sc[tid] = sc;
        s_sh[tid] = fmaf(-mean, sc, beta[tid]);
    }
    __syncthreads();

    // ---- producers -------------------------------------------------------
    auto prodB = [&](int buf, int kc) {
        const unsigned bb = sb + buf * STG_ + APL_;
        #pragma unroll
        for (int t = 0; t < 2; ++t) {
            const int idx = tid + t * 256;
            const int row = idx >> 2, c = idx & 3;
            cp16(bb + row * 80 + c * 16,
                 Wh + (size_t)(n0 + row) * K + kc * 32 + c * 8);
        }
    };
    auto prodA1 = [&](int buf, int kc) {          // FIRST: cp.async fp16
        const unsigned ab = sb + buf * STG_;
        #pragma unroll
        for (int t = 0; t < 2; ++t) {
            const int idx = tid + t * 256;
            const int row = idx >> 2, c = idx & 3;
            cp16(ab + row * 80 + c * 16,
                 g_xh + (m0 + row) * (size_t)K + kc * 32 + c * 8);
        }
    };
    // SECOND: manual A producer (LDG fp16 y1 -> BN+ReLU -> fp16 STS)
    uint4 areg[2];
    auto ldA2 = [&](int kc) {
        const int r = tid >> 1, hf = tid & 1;
        const __half* src = g_y1h + (m0 + r) * (size_t)K + kc * 32 + hf * 16;
        areg[0] = *(const uint4*)(src);
        areg[1] = *(const uint4*)(src + 8);
    };
    auto stA2 = [&](int buf, int kc) {
        const int r = tid >> 1, hf = tid & 1;
        const int kk = kc * 32 + hf * 16;
        const unsigned* ha = (const unsigned*)areg;
        unsigned hv[8];
        #pragma unroll
        for (int w = 0; w < 8; ++w) {
            __half2 hp = *(const __half2*)&ha[w];
            float2 f = __half22float2(hp);
            const int kb = kk + w * 2;
            f.x = fmaxf(fmaf(f.x, s_sc[kb + 0], s_sh[kb + 0]), 0.f);
            f.y = fmaxf(fmaf(f.y, s_sc[kb + 1], s_sh[kb + 1]), 0.f);
            hv[w] = h2u(__floats2half2_rn(f.x, f.y));
        }
        char* ad = sm + buf * STG_ + r * 80 + hf * 32;
        *(uint4*)(ad)      = make_uint4(hv[0], hv[1], hv[2], hv[3]);
        *(uint4*)(ad + 16) = make_uint4(hv[4], hv[5], hv[6], hv[7]);
    };

    // ---- ldmatrix per-lane base offsets ----------------------------------
    const unsigned aRowOff =
        (unsigned)((warpM * 64 + (lane & 15)) * 80 + ((lane >> 4) & 1) * 16);
    const unsigned bRowOff =
        (unsigned)((warpN * 32 + ((lane >> 4) << 3) + (lane & 7)) * 80 +
                   ((lane >> 3) & 1) * 16);

    float acc[4][4][4];
    #pragma unroll
    for (int i = 0; i < 4; ++i)
        #pragma unroll
        for (int j = 0; j < 4; ++j)
            #pragma unroll
            for (int q = 0; q < 4; ++q) acc[i][j][q] = 0.f;

    // ---- prologue: fill stages 0,1,2 (one cp group each) -----------------
    #pragma unroll
    for (int p = 0; p < 3; ++p) {
        if (SECOND) { ldA2(p); stA2(p, p); }
        else        prodA1(p, p);
        prodB(p, p);
        cp_commit();
    }
    if (SECOND && NC > 3) ldA2(3);

    // ---- main loop (4-stage; one commit per iteration) -------------------
    for (int kc = 0; kc < NC; ++kc) {
        cp_wait<2>();
        __syncthreads();
        const int nbuf = (kc + 3) & 3;
        if (kc + 3 < NC) {
            prodB(nbuf, kc + 3);
            if (!SECOND) prodA1(nbuf, kc + 3);
        }
        cp_commit();

        const unsigned base = sb + (kc & 3) * STG_;
        const unsigned aH = base + aRowOff;
        const unsigned bH = base + APL_ + bRowOff;

        #pragma unroll
        for (int k16 = 0; k16 < 2; ++k16) {
            const unsigned ko = k16 * 32;
            unsigned bh[8];
            ldsm4(bh + 0, bH + ko);
            ldsm4(bh + 4, bH + ko + 16 * 80);
            #pragma unroll
            for (int i = 0; i < 4; ++i) {
                unsigned ah[4];
                ldsm4(ah, aH + ko + i * (16 * 80));
                #pragma unroll
                for (int j = 0; j < 4; ++j)
                    mma16816(acc[i][j], ah, bh[2 * j], bh[2 * j + 1]);
            }
        }

        if (SECOND && kc + 3 < NC) {
            stA2(nbuf, kc + 3);                  // LDG latency hidden by MMAs
            if (kc + 4 < NC) ldA2(kc + 4);
        }
    }

    // ---- epilogue: regs -> smem C-tile -> coalesced store + BN stats -----
    __syncthreads();                      // all tile reads done; reuse smem
    float* Ct = (float*)sm;               // 128 x 132 fp32
    const int g = lane >> 2, q = lane & 3;
    if (tid < 128) { redsum[tid] = 0.f; redsq[tid] = 0.f; }
    #pragma unroll
    for (int i = 0; i < 4; ++i) {
        const int r0 = warpM * 64 + i * 16 + g;
        #pragma unroll
        for (int j = 0; j < 4; ++j) {
            const int c0 = warpN * 32 + j * 8 + q * 2;
            *(float2*)&Ct[r0 * 132 + c0]       = make_float2(acc[i][j][0], acc[i][j][1]);
            *(float2*)&Ct[(r0 + 8) * 132 + c0] = make_float2(acc[i][j][2], acc[i][j][3]);
        }
    }
    __syncthreads();

    float4 s4 = make_float4(0, 0, 0, 0), q4v = make_float4(0, 0, 0, 0);
    const int cc = (tid & 31) * 4;
    #pragma unroll
    for (int p = 0; p < 16; ++p) {
        const int row = (tid + p * 256) >> 5;
        float4 v = *(float4*)&Ct[row * 132 + cc];
        if (SECOND) {
            *(float4*)(outp + (m0 + row) * NOUT + n0 + cc) = v;
        } else {
            uint2 pk = make_uint2(h2u(__floats2half2_rn(v.x, v.y)),
                                  h2u(__floats2half2_rn(v.z, v.w)));
            *(uint2*)(g_y1h + (m0 + row) * (size_t)NOUT + n0 + cc) = pk;
        }
        s4.x += v.x; s4.y += v.y; s4.z += v.z; s4.w += v.w;
        q4v.x = fmaf(v.x, v.x, q4v.x); q4v.y = fmaf(v.y, v.y, q4v.y);
        q4v.z = fmaf(v.z, v.z, q4v.z); q4v.w = fmaf(v.w, v.w, q4v.w);
    }
    atomicAdd(&redsum[cc + 0], s4.x); atomicAdd(&redsum[cc + 1], s4.y);
    atomicAdd(&redsum[cc + 2], s4.z); atomicAdd(&redsum[cc + 3], s4.w);
    atomicAdd(&redsq [cc + 0], q4v.x); atomicAdd(&redsq [cc + 1], q4v.y);
    atomicAdd(&redsq [cc + 2], q4v.z); atomicAdd(&redsq [cc + 3], q4v.w);
    __syncthreads();
    if (tid < 128) {
        atomicAdd(&gsum[n0 + tid], redsum[tid]);
        atomicAdd(&gsq [n0 + tid], redsq [tid]);
    }
}

// ---------------------------------------------------------------------------
// final BN2 + ReLU, in-place on d_out [MROWS, 128]; coefs computed per block
// ---------------------------------------------------------------------------
__global__ void bn_out_kernel(float* __restrict__ out,
                              const float* __restrict__ gamma2,
                              const float* __restrict__ beta2)
{
    __shared__ float s2[M2_], t2[M2_];
    const int tid = threadIdx.x;
    if (tid < M2_) {
        const float invC = 1.0f / (float)MROWS;
        float mean = g_sum2[tid] * invC;
        float var  = g_sq2[tid] * invC - mean * mean;
        float sc   = gamma2[tid] * rsqrtf(var + 1e-5f);
        s2[tid] = sc;
        t2[tid] = fmaf(-mean, sc, beta2[tid]);
    }
    __syncthreads();

    const size_t idx = (size_t)blockIdx.x * blockDim.x + tid;  // float4 idx
    float4 v = ((float4*)out)[idx];
    const int c = ((int)(idx * 4)) & (M2_ - 1);
    v.x = fmaxf(fmaf(v.x, s2[c + 0], t2[c + 0]), 0.f);
    v.y = fmaxf(fmaf(v.y, s2[c + 1], t2[c + 1]), 0.f);
    v.z = fmaxf(fmaf(v.z, s2[c + 2], t2[c + 2]), 0.f);
    v.w = fmaxf(fmaf(v.w, s2[c + 3], t2[c + 3]), 0.f);
    ((float4*)out)[idx] = v;
}

// ---------------------------------------------------------------------------
// Launch — GEMM1 at index 3 (= ncu's sampled launch)
// ---------------------------------------------------------------------------
extern "C" void kernel_launch(void* const* d_in, const int* in_sizes, int n_in,
                              void* d_out, int out_size)
{
    const float* txyz   = (const float*)d_in[0];
    const float* sxyz   = (const float*)d_in[1];
    const float* sfeat  = (const float*)d_in[2];
    const float* skip   = (const float*)d_in[3];
    const float* W1     = (const float*)d_in[4];
    const float* gamma1 = (const float*)d_in[5];
    const float* beta1  = (const float*)d_in[6];
    const float* W2     = (const float*)d_in[7];
    const float* gamma2 = (const float*)d_in[8];
    const float* beta2  = (const float*)d_in[9];
    float* out = (float*)d_out;

    const int SMEM1 = SCO_ + 2 * CIN_ * 4;   // 86016
    const int SMEM2 = SCO_ + 2 * M1_ * 4;    // 84992
    cudaFuncSetAttribute(gemm_mma_kernel<CIN_, M1_, false>,
                         cudaFuncAttributeMaxDynamicSharedMemorySize, SMEM1);
    cudaFuncSetAttribute(gemm_mma_kernel<M1_, M2_, true>,
                         cudaFuncAttributeMaxDynamicSharedMemorySize, SMEM2);

    const int prepBlocks = (SKIPH2 + M1_ * CIN_ + M2_ * M1_ + 255) / 256;  // 16896
    prep_kernel<<<prepBlocks, 256>>>(W1, W2, skip);                         // 0
    knn_kernel<<<dim3(N_ / 256, B_), 128>>>(txyz, sxyz);                    // 1
    gather_kernel<<<MROWS / 8, 256>>>(sfeat);                               // 2
    gemm_mma_kernel<CIN_, M1_, false><<<dim3(2, MROWS / 128), 256, SMEM1>>>(
        nullptr, nullptr, nullptr);                                         // 3 <- profiled
    gemm_mma_kernel<M1_, M2_, true><<<dim3(1, MROWS / 128), 256, SMEM2>>>(
        out, gamma1, beta1);                                                // 4
    bn_out_kernel<<<(MROWS * M2_ / 4) / 256, 256>>>(out, gamma2, beta2);    // 5
}